// round 16
// baseline (speedup 1.0000x reference)
#include <cuda_runtime.h>
#include <cuda_fp16.h>
#include <cstdint>
#include <cstddef>

// ---------------------------------------------------------------------------
// GraphSAGE on sm_100 (base target):
//   init (deg clear + W fp16 conv + feature fp16 convert, one kernel)
//   count -> single-pass scan -> fill
//   3x [ agg (fp16 uint4 gather, half-warp per edge) ; GEMM fp16 1-term ]
//   layer2 GEMM fuses the final 128->64 linear in-CTA.
//
// ALL activations are plain fp16 planes [node][k]; rel_err budget ~6.4e-4
// (deterministic inputs).  GEMM: all-cp.async 3-stage pipeline (1 barrier
// per chunk), 512 thr, 2 CTA/SM, 99.3KB smem.
// ---------------------------------------------------------------------------

#define N_NODES 100000
#define N_EDGES 600000
#define F 128
#define PLANE ((size_t)(N_NODES + 128) * F)  // padded so GEMM tiles never OOB

// ---- scratch ---------------------------------------------------------------
__device__ __half g_f[PLANE];    // fp16 features
__device__ __half g_h0[PLANE];   // h ping
__device__ __half g_h1[PLANE];   // h pong
__device__ __half g_a[PLANE];    // neighbor means
__device__ float g_invdeg[N_NODES];
__device__ int   g_deg[N_NODES];
__device__ int   g_cursor[N_NODES];
__device__ int   g_csr_off[N_NODES + 1];
__device__ int   g_csr_src[N_EDGES];
__device__ int   g_blockagg[128];
#define W_TOTAL (3 * 128 * 256 + 64 * 128)
__device__ __half g_wh[W_TOTAL];

// ---- helpers ---------------------------------------------------------------
__device__ __forceinline__ uint32_t smem_u32(const void* p) {
    uint32_t a;
    asm("{ .reg .u64 t; cvta.to.shared.u64 t, %1; cvt.u32.u64 %0, t; }"
        : "=r"(a) : "l"(p));
    return a;
}
__device__ __forceinline__ void mma16816(float* c, const uint32_t* a,
                                         const uint32_t* b) {
    asm volatile(
        "mma.sync.aligned.m16n8k16.row.col.f32.f16.f16.f32 "
        "{%0,%1,%2,%3}, {%4,%5,%6,%7}, {%8,%9}, {%0,%1,%2,%3};"
        : "+f"(c[0]), "+f"(c[1]), "+f"(c[2]), "+f"(c[3])
        : "r"(a[0]), "r"(a[1]), "r"(a[2]), "r"(a[3]), "r"(b[0]), "r"(b[1]));
}
__device__ __forceinline__ void ldsm4(uint32_t* r, uint32_t addr) {
    asm volatile(
        "ldmatrix.sync.aligned.m8n8.x4.shared.b16 {%0,%1,%2,%3}, [%4];"
        : "=r"(r[0]), "=r"(r[1]), "=r"(r[2]), "=r"(r[3]) : "r"(addr));
}
#define SWZ(o) ((o) ^ (((o) >> 3) & 0x70))
__device__ __forceinline__ uint32_t pk_h(float a, float b) {
    __half2 h = __floats2half2_rn(a, b);
    return *(uint32_t*)&h;
}
__device__ __forceinline__ float2 up_h(uint32_t p) {
    return __half22float2(*(__half2*)&p);
}
__device__ __forceinline__ void cp16(uint32_t d, const void* s) {
    asm volatile("cp.async.cg.shared.global [%0], [%1], 16;" ::"r"(d), "l"(s)
                 : "memory");
}
#define CP_COMMIT asm volatile("cp.async.commit_group;" ::: "memory")
#define CP_WAIT(n) asm volatile("cp.async.wait_group %0;" ::"n"(n) : "memory")

// ---- init: deg clear + weight fp16 conv + feature fp16 convert -------------
__global__ void init_kernel(const float* feats, const float* w0s,
                            const float* w0n, const float* w1s,
                            const float* w1n, const float* w2s,
                            const float* w2n, const float* wo) {
    int i = blockIdx.x * blockDim.x + threadIdx.x;
    if (i < N_NODES) g_deg[i] = 0;
    if (i < 128) g_blockagg[i] = 0;
    if (i < W_TOTAL) {
        float w;
        if (i < 3 * 32768) {
            int l = i >> 15, local = i & 32767;
            int n = local >> 8, k = local & 255;
            const float* ws = (l == 0) ? w0s : (l == 1) ? w1s : w2s;
            const float* wn = (l == 0) ? w0n : (l == 1) ? w1n : w2n;
            w = (k < 128) ? ws[k * 128 + n] : wn[(k - 128) * 128 + n];
        } else {
            int local = i - 3 * 32768;
            int n = local >> 7, k = local & 127;
            w = wo[k * 64 + n];
        }
        g_wh[i] = __float2half_rn(w);
    }
    if (i < N_NODES * (F / 4)) {
        float4 v = ((const float4*)feats)[i];
        ((uint2*)g_f)[i] = make_uint2(pk_h(v.x, v.y), pk_h(v.z, v.w));
    }
}
__global__ void count_kernel(const int* __restrict__ dst) {
    int e = blockIdx.x * blockDim.x + threadIdx.x;
    if (e < N_EDGES) atomicAdd(&g_deg[dst[e]], 1);
}
// single-pass scan: publish block aggregate, warp-parallel lookback; seeds
// the fill cursors with the offsets.
__global__ void scanall_kernel() {
    __shared__ int ws[32];
    __shared__ int s_base;
    const int tid = threadIdx.x, lane = tid & 31, w = tid >> 5;
    const int bid = blockIdx.x;
    const int i = bid * 1024 + tid;
    const int x = (i < N_NODES) ? g_deg[i] : 0;
    int inc = x;
    #pragma unroll
    for (int o = 1; o < 32; o <<= 1) {
        int v = __shfl_up_sync(0xFFFFFFFF, inc, o);
        if (lane >= o) inc += v;
    }
    if (lane == 31) ws[w] = inc;
    __syncthreads();
    if (w == 0) {
        int s = ws[lane];
        #pragma unroll
        for (int o = 1; o < 32; o <<= 1) {
            int v = __shfl_up_sync(0xFFFFFFFF, s, o);
            if (lane >= o) s += v;
        }
        ws[lane] = s;
    }
    __syncthreads();
    const int local_excl = ((w == 0) ? 0 : ws[w - 1]) + inc - x;
    const int T = ws[31];
    if (tid == 0) atomicExch(&g_blockagg[bid], T | (1 << 30));
    if (w == 0) {
        int sum = 0;
        for (int j = lane; j < bid; j += 32) {
            int v;
            do { v = atomicAdd(&g_blockagg[j], 0); } while (v == 0);
            sum += v & 0x3FFFFFFF;
        }
        #pragma unroll
        for (int o = 16; o > 0; o >>= 1)
            sum += __shfl_down_sync(0xFFFFFFFF, sum, o);
        if (lane == 0) s_base = sum;
    }
    __syncthreads();
    if (i < N_NODES) {
        const int off = s_base + local_excl;
        g_csr_off[i] = off;
        g_cursor[i] = off;
        g_invdeg[i] = 1.0f / fmaxf((float)x, 1.0f);
    }
    if (i == 0) g_csr_off[N_NODES] = N_EDGES;
}
__global__ void fill_kernel(const int* __restrict__ src,
                            const int* __restrict__ dst) {
    int e = blockIdx.x * blockDim.x + threadIdx.x;
    if (e < N_EDGES) {
        int pos = atomicAdd(&g_cursor[dst[e]], 1);
        g_csr_src[pos] = src[e];
    }
}

// ---- aggregation: warp/node; uint4 loads, half-warp per edge ---------------
// lanes 0-15 process even edges, 16-31 odd edges; lane owns 8 features
// (16B).  shfl_down(16) combines the halves; lanes 0-15 write uint4.
__global__ void agg_kernel(const __half* __restrict__ X) {
    int w = (blockIdx.x * blockDim.x + threadIdx.x) >> 5;
    int lane = threadIdx.x & 31;
    if (w >= N_NODES) return;
    const int beg = g_csr_off[w], end = g_csr_off[w + 1];
    const int half = lane >> 4, li = lane & 15;
    float acc[8];
    #pragma unroll
    for (int j = 0; j < 8; j++) acc[j] = 0.f;
    for (int e = beg + half; e < end; e += 2) {
        int s = g_csr_src[e];
        uint4 v = *(const uint4*)(X + (size_t)s * F + li * 8);
        float2 a = up_h(v.x), b = up_h(v.y), c = up_h(v.z), d = up_h(v.w);
        acc[0] += a.x; acc[1] += a.y; acc[2] += b.x; acc[3] += b.y;
        acc[4] += c.x; acc[5] += c.y; acc[6] += d.x; acc[7] += d.y;
    }
    #pragma unroll
    for (int j = 0; j < 8; j++)
        acc[j] += __shfl_down_sync(0xFFFFFFFF, acc[j], 16);
    if (half == 0) {
        float inv = g_invdeg[w];
        uint4 o;
        o.x = pk_h(acc[0] * inv, acc[1] * inv);
        o.y = pk_h(acc[2] * inv, acc[3] * inv);
        o.z = pk_h(acc[4] * inv, acc[5] * inv);
        o.w = pk_h(acc[6] * inv, acc[7] * inv);
        *(uint4*)(g_a + (size_t)w * F + li * 8) = o;
    }
}

// ---- all-cp.async fp16 1-term GEMM, 3-stage pipeline, 2 CTA/SM --------------
// Y = [self | agg] @ W_f16 + bias (+relu); activations plain fp16 planes.
// FUSE: (Y tile) @ W_out + bout -> Yout; W_out streams into B-buffer 1
// (dead after iter 1; chunk 3 reuses buffer 0).
template <bool RELU, bool FUSE>
__global__ void __launch_bounds__(512, 2) sage_mma(
    const __half* __restrict__ S, const __half* __restrict__ N,
    const __half* __restrict__ Wh,
    const float* __restrict__ bsv, const float* __restrict__ bnv,
    __half* __restrict__ Y,
    const __half* __restrict__ WOh,
    const float* __restrict__ bout, float* __restrict__ Yout) {
    constexpr int OFF_B = 49152;            // after 3 A bufs (16KB each)
    constexpr int OFF_BIAS = OFF_B + 49152; // 98304; total smem 99,328

    extern __shared__ char smc[];
    const uint32_t sb = smem_u32(smc);
    const int tid = threadIdx.x, wid = tid >> 5, lane = tid & 31;
    const int node0 = blockIdx.x * 128;
    float* sB = (float*)(smc + OFF_BIAS);
    float* sBo = (float*)(smc + OFF_BIAS + 512);
    if (tid < 128) sB[tid] = bsv[tid] + bnv[tid];
    if (FUSE && tid < 64) sBo[tid] = bout[tid];

    // issue chunk c (A + B) as one cp.async group; buffers cycle mod 3
    auto issueChunk = [&](int c) {
        const __half* a = (c >= 2) ? N : S;
        const size_t kof = (size_t)(c & 1) * 64;
        const uint32_t ab = sb + (c % 3) * 16384;
        #pragma unroll
        for (int g = tid; g < 1024; g += 512) {
            int r = g >> 3, kk = (g & 7) * 8;
            cp16(ab + SWZ((uint32_t)(r * 128 + kk * 2)),
                 a + (size_t)(node0 + r) * F + kof + kk);
        }
        const uint32_t bb = sb + OFF_B + (c % 3) * 16384;
        #pragma unroll
        for (int g = tid; g < 1024; g += 512) {
            int n = g >> 3, kk = (g & 7) * 8;
            cp16(bb + SWZ((uint32_t)(n * 128 + kk * 2)),
                 Wh + n * 256 + c * 64 + kk);
        }
        CP_COMMIT;
    };

    // lane-invariant ldmatrix bases (4 warps N x 4 warps M, MI=2)
    const int wn = (wid & 3) * 32;
    const int wm = (wid >> 2) * 32;
    const int ar = wm + (lane & 15);
    const uint32_t a_base = (uint32_t)(ar * 128 + (lane >> 4) * 16);
    const uint32_t a_mask = (uint32_t)((ar & 7) << 4);
    const int br = wn + (lane & 7) + ((lane >> 4) << 3);
    const uint32_t b_base = (uint32_t)(br * 128 + ((lane >> 3) & 1) * 16);
    const uint32_t b_mask = (uint32_t)((br & 7) << 4);

    float acc[2][4][4];
    #pragma unroll
    for (int mi = 0; mi < 2; mi++)
        #pragma unroll
        for (int ni = 0; ni < 4; ni++)
            #pragma unroll
            for (int q = 0; q < 4; q++) acc[mi][ni][q] = 0.f;

    issueChunk(0);
    issueChunk(1);

    #pragma unroll 1
    for (int c = 0; c < 4; c++) {
        if (c < 3) CP_WAIT(1); else CP_WAIT(0);
        __syncthreads();
        // issue into a buffer last consumed at iter c-1 (fenced by the
        // barrier above) -> single barrier per chunk.
        if (c < 2) {
            issueChunk(c + 2);
        } else if (FUSE && c == 2) {
            // W_out -> B buffer 1 (chunk 1's, dead; chunk 3 uses buffer 0)
            #pragma unroll
            for (int g = tid; g < 1024; g += 512) {
                int n = g >> 4, kk = (g & 15) * 8;
                int chunk = kk >> 6, lc = kk & 63;
                uint32_t doff = (uint32_t)(OFF_B + 16384 + chunk * 8192) +
                                SWZ((uint32_t)(n * 128 + lc * 2));
                cp16(sb + doff, WOh + n * 128 + kk);
            }
            CP_COMMIT;
        }
        const uint32_t ab = sb + (c % 3) * 16384;
        const uint32_t bb = sb + OFF_B + (c % 3) * 16384;
        #pragma unroll
        for (int ks = 0; ks < 4; ks++) {
            uint32_t ah[2][4], bh[4][2];
            const uint32_t ka = (a_base + ks * 32) ^ a_mask;
            #pragma unroll
            for (int mi = 0; mi < 2; mi++)
                ldsm4(ah[mi], ab + ka + mi * 2048);
            const uint32_t kb = (b_base + ks * 32) ^ b_mask;
            ldsm4(&bh[0][0], bb + kb);
            ldsm4(&bh[2][0], bb + kb + 2048);
            #pragma unroll
            for (int mi = 0; mi < 2; mi++)
                #pragma unroll
                for (int ni = 0; ni < 4; ni++)
                    mma16816(acc[mi][ni], ah[mi], bh[ni]);
        }
    }

    const int erow = wm + (lane >> 2);
    const int ecol = wn + (lane & 3) * 2;

    if (!FUSE) {
        // epilogue: bias (+relu) -> fp16 plane
        #pragma unroll
        for (int mi = 0; mi < 2; mi++) {
            #pragma unroll
            for (int h = 0; h < 2; h++) {
                const int gr = node0 + erow + mi * 16 + h * 8;
                if (gr >= N_NODES) continue;
                #pragma unroll
                for (int ni = 0; ni < 4; ni++) {
                    const int cc = ecol + ni * 8;
                    float ox = acc[mi][ni][2 * h] + sB[cc];
                    float oy = acc[mi][ni][2 * h + 1] + sB[cc + 1];
                    if (RELU) { ox = fmaxf(ox, 0.f); oy = fmaxf(oy, 0.f); }
                    *(uint32_t*)((char*)Y + ((size_t)gr * F + cc) * 2) =
                        pk_h(ox, oy);
                }
            }
        }
        return;
    }

    // ---- FUSE: pack h2 tile (bias, no relu) into smem fp16 ----------------
    // A buffers are all dead now: chunk c of h2 -> smc + c*16384 (A0,A1).
    __syncthreads();
    #pragma unroll
    for (int mi = 0; mi < 2; mi++) {
        #pragma unroll
        for (int h = 0; h < 2; h++) {
            const int r = erow + mi * 16 + h * 8;
            #pragma unroll
            for (int ni = 0; ni < 4; ni++) {
                const int cc = ecol + ni * 8;
                float ox = acc[mi][ni][2 * h] + sB[cc];
                float oy = acc[mi][ni][2 * h + 1] + sB[cc + 1];
                const int chunk = cc >> 6, lc = cc & 63;
                *(uint32_t*)(smc + chunk * 16384 +
                             SWZ((uint32_t)(r * 128 + lc * 2))) = pk_h(ox, oy);
            }
        }
    }
    __syncthreads();

    // ---- FUSE: h2 @ W_out + bout -> Yout (128 x 64, K=128) ----------------
    const int wn2 = (wid & 1) * 32;
    const int wm2 = (wid >> 1) * 16;
    const int ar2 = wm2 + (lane & 15);
    const uint32_t a_base2 = (uint32_t)(ar2 * 128 + (lane >> 4) * 16);
    const uint32_t a_mask2 = (uint32_t)((ar2 & 7) << 4);
    const int br2 = wn2 + (lane & 7) + ((lane >> 4) << 3);
    const uint32_t b_base2 = (uint32_t)(br2 * 128 + ((lane >> 3) & 1) * 16);
    const uint32_t b_mask2 = (uint32_t)((br2 & 7) << 4);

    float acc2[4][4];
    #pragma unroll
    for (int ni = 0; ni < 4; ni++)
        #pragma unroll
        for (int q = 0; q < 4; q++) acc2[ni][q] = 0.f;

    #pragma unroll
    for (int c = 0; c < 2; c++) {
        const uint32_t ab = sb + c * 16384;
        const uint32_t bb = sb + OFF_B + 16384 + c * 8192;  // WO in B buf 1
        #pragma unroll
        for (int ks = 0; ks < 4; ks++) {
            uint32_t ah[4], bh[4][2];
            ldsm4(ah, ab + ((a_base2 + ks * 32) ^ a_mask2));
            const uint32_t kb = (b_base2 + ks * 32) ^ b_mask2;
            ldsm4(&bh[0][0], bb + kb);
            ldsm4(&bh[2][0], bb + kb + 2048);
            #pragma unroll
            for (int ni = 0; ni < 4; ni++) mma16816(acc2[ni], ah, bh[ni]);
        }
    }

    const int erow2 = wm2 + (lane >> 2);
    const int ecol2 = wn2 + (lane & 3) * 2;
    #pragma unroll
    for (int h = 0; h < 2; h++) {
        const int gr = node0 + erow2 + h * 8;
        if (gr >= N_NODES) continue;
        float* yp = Yout + (size_t)gr * 64;
        #pragma unroll
        for (int ni = 0; ni < 4; ni++) {
            float2 o;
            o.x = acc2[ni][2 * h] + sBo[ecol2 + ni * 8];
            o.y = acc2[ni][2 * h + 1] + sBo[ecol2 + ni * 8 + 1];
            *(float2*)(yp + ecol2 + ni * 8) = o;
        }
    }
}

// ---------------------------------------------------------------------------
extern "C" void kernel_launch(void* const* d_in, const int* in_sizes, int n_in,
                              void* d_out, int out_size) {
    const float* feats = (const float*)d_in[0];
    const int* src = (const int*)d_in[1];
    const int* dst = (const int*)d_in[2];
    const float* Ws[3] = {(const float*)d_in[3], (const float*)d_in[7],
                          (const float*)d_in[11]};
    const float* bs[3] = {(const float*)d_in[4], (const float*)d_in[8],
                          (const float*)d_in[12]};
    const float* Wn[3] = {(const float*)d_in[5], (const float*)d_in[9],
                          (const float*)d_in[13]};
    const float* bn[3] = {(const float*)d_in[6], (const float*)d_in[10],
                          (const float*)d_in[14]};
    const float* Wout = (const float*)d_in[15];
    const float* bout = (const float*)d_in[16];

    __half *f, *h0, *h1, *a, *wh;
    cudaGetSymbolAddress((void**)&f, g_f);
    cudaGetSymbolAddress((void**)&h0, g_h0);
    cudaGetSymbolAddress((void**)&h1, g_h1);
    cudaGetSymbolAddress((void**)&a, g_a);
    cudaGetSymbolAddress((void**)&wh, g_wh);

    const int SMEM_GEMM = 98304 + 1024;  // 99,328 -> 2 CTAs/SM

    auto kRelu = sage_mma<true, false>;
    auto kFuse = sage_mma<false, true>;
    cudaFuncSetAttribute((const void*)kRelu,
                         cudaFuncAttributeMaxDynamicSharedMemorySize, SMEM_GEMM);
    cudaFuncSetAttribute((const void*)kFuse,
                         cudaFuncAttributeMaxDynamicSharedMemorySize, SMEM_GEMM);

    const int NPART = (N_NODES + 1023) / 1024;  // 98
    init_kernel<<<(N_NODES * 32 + 255) / 256, 256>>>(
        feats, Ws[0], Wn[0], Ws[1], Wn[1], Ws[2], Wn[2], Wout);
    count_kernel<<<(N_EDGES + 255) / 256, 256>>>(dst);
    scanall_kernel<<<NPART, 1024>>>();
    fill_kernel<<<(N_EDGES + 255) / 256, 256>>>(src, dst);

    const int AGG_BLOCKS = (N_NODES * 32 + 255) / 256;
    const int GB = (N_NODES + 127) / 128;  // 782

    agg_kernel<<<AGG_BLOCKS, 256>>>(f);
    kRelu<<<GB, 512, SMEM_GEMM>>>(f, a, wh, bs[0], bn[0], h0, nullptr, nullptr,
                                  nullptr);
    agg_kernel<<<AGG_BLOCKS, 256>>>(h0);
    kRelu<<<GB, 512, SMEM_GEMM>>>(h0, a, wh + 32768, bs[1], bn[1], h1, nullptr,
                                  nullptr, nullptr);
    agg_kernel<<<AGG_BLOCKS, 256>>>(h1);
    kFuse<<<GB, 512, SMEM_GEMM>>>(h1, a, wh + 65536, bs[2], bn[2], nullptr,
                                  wh + 98304, bout, (float*)d_out);
}

// round 17
// speedup vs baseline: 1.0406x; 1.0406x over previous
#include <cuda_runtime.h>
#include <cuda_fp16.h>
#include <cstdint>
#include <cstddef>

// ---------------------------------------------------------------------------
// GraphSAGE on sm_100 (base target):
//   init (deg clear + W fp16 conv + feature fp16 convert, one kernel)
//   count -> single-pass scan -> fill
//   3x [ agg (fp16 gather, warp/node, uint2 loads — R14 form) ;
//        GEMM fp16 1-term, 3-stage cp.async pipeline ]
//   layer2 GEMM fuses the final 128->64 linear in-CTA.
//
// ALL activations are plain fp16 planes [node][k]; rel_err 6.40e-4
// (deterministic).  GEMM: 3 A bufs + 3 B bufs, ONE barrier per chunk,
// 512 thr, 2 CTA/SM, 99.3KB smem.
// ---------------------------------------------------------------------------

#define N_NODES 100000
#define N_EDGES 600000
#define F 128
#define PLANE ((size_t)(N_NODES + 128) * F)  // padded so GEMM tiles never OOB

// ---- scratch ---------------------------------------------------------------
__device__ __half g_f[PLANE];    // fp16 features
__device__ __half g_h0[PLANE];   // h ping
__device__ __half g_h1[PLANE];   // h pong
__device__ __half g_a[PLANE];    // neighbor means
__device__ float g_invdeg[N_NODES];
__device__ int   g_deg[N_NODES];
__device__ int   g_cursor[N_NODES];
__device__ int   g_csr_off[N_NODES + 1];
__device__ int   g_csr_src[N_EDGES];
__device__ int   g_blockagg[128];
#define W_TOTAL (3 * 128 * 256 + 64 * 128)
__device__ __half g_wh[W_TOTAL];

// ---- helpers ---------------------------------------------------------------
__device__ __forceinline__ uint32_t smem_u32(const void* p) {
    uint32_t a;
    asm("{ .reg .u64 t; cvta.to.shared.u64 t, %1; cvt.u32.u64 %0, t; }"
        : "=r"(a) : "l"(p));
    return a;
}
__device__ __forceinline__ void mma16816(float* c, const uint32_t* a,
                                         const uint32_t* b) {
    asm volatile(
        "mma.sync.aligned.m16n8k16.row.col.f32.f16.f16.f32 "
        "{%0,%1,%2,%3}, {%4,%5,%6,%7}, {%8,%9}, {%0,%1,%2,%3};"
        : "+f"(c[0]), "+f"(c[1]), "+f"(c[2]), "+f"(c[3])
        : "r"(a[0]), "r"(a[1]), "r"(a[2]), "r"(a[3]), "r"(b[0]), "r"(b[1]));
}
__device__ __forceinline__ void ldsm4(uint32_t* r, uint32_t addr) {
    asm volatile(
        "ldmatrix.sync.aligned.m8n8.x4.shared.b16 {%0,%1,%2,%3}, [%4];"
        : "=r"(r[0]), "=r"(r[1]), "=r"(r[2]), "=r"(r[3]) : "r"(addr));
}
#define SWZ(o) ((o) ^ (((o) >> 3) & 0x70))
__device__ __forceinline__ uint32_t pk_h(float a, float b) {
    __half2 h = __floats2half2_rn(a, b);
    return *(uint32_t*)&h;
}
__device__ __forceinline__ float2 up_h(uint32_t p) {
    return __half22float2(*(__half2*)&p);
}
__device__ __forceinline__ void cp16(uint32_t d, const void* s) {
    asm volatile("cp.async.cg.shared.global [%0], [%1], 16;" ::"r"(d), "l"(s)
                 : "memory");
}
#define CP_COMMIT asm volatile("cp.async.commit_group;" ::: "memory")
#define CP_WAIT(n) asm volatile("cp.async.wait_group %0;" ::"n"(n) : "memory")

// ---- init: deg clear + weight fp16 conv + feature fp16 convert -------------
__global__ void init_kernel(const float* feats, const float* w0s,
                            const float* w0n, const float* w1s,
                            const float* w1n, const float* w2s,
                            const float* w2n, const float* wo) {
    int i = blockIdx.x * blockDim.x + threadIdx.x;
    if (i < N_NODES) g_deg[i] = 0;
    if (i < 128) g_blockagg[i] = 0;
    if (i < W_TOTAL) {
        float w;
        if (i < 3 * 32768) {
            int l = i >> 15, local = i & 32767;
            int n = local >> 8, k = local & 255;
            const float* ws = (l == 0) ? w0s : (l == 1) ? w1s : w2s;
            const float* wn = (l == 0) ? w0n : (l == 1) ? w1n : w2n;
            w = (k < 128) ? ws[k * 128 + n] : wn[(k - 128) * 128 + n];
        } else {
            int local = i - 3 * 32768;
            int n = local >> 7, k = local & 127;
            w = wo[k * 64 + n];
        }
        g_wh[i] = __float2half_rn(w);
    }
    if (i < N_NODES * (F / 4)) {
        float4 v = ((const float4*)feats)[i];
        ((uint2*)g_f)[i] = make_uint2(pk_h(v.x, v.y), pk_h(v.z, v.w));
    }
}
__global__ void count_kernel(const int* __restrict__ dst) {
    int e = blockIdx.x * blockDim.x + threadIdx.x;
    if (e < N_EDGES) atomicAdd(&g_deg[dst[e]], 1);
}
// single-pass scan: publish block aggregate, warp-parallel lookback; seeds
// the fill cursors with the offsets.
__global__ void scanall_kernel() {
    __shared__ int ws[32];
    __shared__ int s_base;
    const int tid = threadIdx.x, lane = tid & 31, w = tid >> 5;
    const int bid = blockIdx.x;
    const int i = bid * 1024 + tid;
    const int x = (i < N_NODES) ? g_deg[i] : 0;
    int inc = x;
    #pragma unroll
    for (int o = 1; o < 32; o <<= 1) {
        int v = __shfl_up_sync(0xFFFFFFFF, inc, o);
        if (lane >= o) inc += v;
    }
    if (lane == 31) ws[w] = inc;
    __syncthreads();
    if (w == 0) {
        int s = ws[lane];
        #pragma unroll
        for (int o = 1; o < 32; o <<= 1) {
            int v = __shfl_up_sync(0xFFFFFFFF, s, o);
            if (lane >= o) s += v;
        }
        ws[lane] = s;
    }
    __syncthreads();
    const int local_excl = ((w == 0) ? 0 : ws[w - 1]) + inc - x;
    const int T = ws[31];
    if (tid == 0) atomicExch(&g_blockagg[bid], T | (1 << 30));
    if (w == 0) {
        int sum = 0;
        for (int j = lane; j < bid; j += 32) {
            int v;
            do { v = atomicAdd(&g_blockagg[j], 0); } while (v == 0);
            sum += v & 0x3FFFFFFF;
        }
        #pragma unroll
        for (int o = 16; o > 0; o >>= 1)
            sum += __shfl_down_sync(0xFFFFFFFF, sum, o);
        if (lane == 0) s_base = sum;
    }
    __syncthreads();
    if (i < N_NODES) {
        const int off = s_base + local_excl;
        g_csr_off[i] = off;
        g_cursor[i] = off;
        g_invdeg[i] = 1.0f / fmaxf((float)x, 1.0f);
    }
    if (i == 0) g_csr_off[N_NODES] = N_EDGES;
}
__global__ void fill_kernel(const int* __restrict__ src,
                            const int* __restrict__ dst) {
    int e = blockIdx.x * blockDim.x + threadIdx.x;
    if (e < N_EDGES) {
        int pos = atomicAdd(&g_cursor[dst[e]], 1);
        g_csr_src[pos] = src[e];
    }
}

// ---- aggregation: warp per node; fp16 gather, mean (R14 form) --------------
__global__ void agg_kernel(const __half* __restrict__ X) {
    int w = (blockIdx.x * blockDim.x + threadIdx.x) >> 5;
    int lane = threadIdx.x & 31;
    if (w >= N_NODES) return;
    int beg = g_csr_off[w], end = g_csr_off[w + 1];
    float4 acc = make_float4(0.f, 0.f, 0.f, 0.f);
    for (int e = beg; e < end; e++) {
        int s = g_csr_src[e];
        uint2 h2 = *(const uint2*)(X + (size_t)s * F + lane * 4);
        float2 a = up_h(h2.x), b = up_h(h2.y);
        acc.x += a.x; acc.y += a.y;
        acc.z += b.x; acc.w += b.y;
    }
    float inv = g_invdeg[w];
    *(uint2*)(g_a + (size_t)w * F + lane * 4) =
        make_uint2(pk_h(acc.x * inv, acc.y * inv),
                   pk_h(acc.z * inv, acc.w * inv));
}

// ---- all-cp.async fp16 1-term GEMM, 3-stage pipeline, 2 CTA/SM --------------
// Y = [self | agg] @ W_f16 + bias (+relu); activations plain fp16 planes.
// FUSE: (Y tile) @ W_out + bout -> Yout; W_out streams into B-buffer 1
// (dead after iter 1; chunk 3 reuses buffer 0).
template <bool RELU, bool FUSE>
__global__ void __launch_bounds__(512, 2) sage_mma(
    const __half* __restrict__ S, const __half* __restrict__ N,
    const __half* __restrict__ Wh,
    const float* __restrict__ bsv, const float* __restrict__ bnv,
    __half* __restrict__ Y,
    const __half* __restrict__ WOh,
    const float* __restrict__ bout, float* __restrict__ Yout) {
    constexpr int OFF_B = 49152;            // after 3 A bufs (16KB each)
    constexpr int OFF_BIAS = OFF_B + 49152; // 98304; total smem 99,328

    extern __shared__ char smc[];
    const uint32_t sb = smem_u32(smc);
    const int tid = threadIdx.x, wid = tid >> 5, lane = tid & 31;
    const int node0 = blockIdx.x * 128;
    float* sB = (float*)(smc + OFF_BIAS);
    float* sBo = (float*)(smc + OFF_BIAS + 512);
    if (tid < 128) sB[tid] = bsv[tid] + bnv[tid];
    if (FUSE && tid < 64) sBo[tid] = bout[tid];

    // issue chunk c (A + B) as one cp.async group; buffers cycle mod 3
    auto issueChunk = [&](int c) {
        const __half* a = (c >= 2) ? N : S;
        const size_t kof = (size_t)(c & 1) * 64;
        const uint32_t ab = sb + (c % 3) * 16384;
        #pragma unroll
        for (int g = tid; g < 1024; g += 512) {
            int r = g >> 3, kk = (g & 7) * 8;
            cp16(ab + SWZ((uint32_t)(r * 128 + kk * 2)),
                 a + (size_t)(node0 + r) * F + kof + kk);
        }
        const uint32_t bb = sb + OFF_B + (c % 3) * 16384;
        #pragma unroll
        for (int g = tid; g < 1024; g += 512) {
            int n = g >> 3, kk = (g & 7) * 8;
            cp16(bb + SWZ((uint32_t)(n * 128 + kk * 2)),
                 Wh + n * 256 + c * 64 + kk);
        }
        CP_COMMIT;
    };

    // lane-invariant ldmatrix bases (4 warps N x 4 warps M, MI=2)
    const int wn = (wid & 3) * 32;
    const int wm = (wid >> 2) * 32;
    const int ar = wm + (lane & 15);
    const uint32_t a_base = (uint32_t)(ar * 128 + (lane >> 4) * 16);
    const uint32_t a_mask = (uint32_t)((ar & 7) << 4);
    const int br = wn + (lane & 7) + ((lane >> 4) << 3);
    const uint32_t b_base = (uint32_t)(br * 128 + ((lane >> 3) & 1) * 16);
    const uint32_t b_mask = (uint32_t)((br & 7) << 4);

    float acc[2][4][4];
    #pragma unroll
    for (int mi = 0; mi < 2; mi++)
        #pragma unroll
        for (int ni = 0; ni < 4; ni++)
            #pragma unroll
            for (int q = 0; q < 4; q++) acc[mi][ni][q] = 0.f;

    issueChunk(0);
    issueChunk(1);

    #pragma unroll 1
    for (int c = 0; c < 4; c++) {
        if (c < 3) CP_WAIT(1); else CP_WAIT(0);
        __syncthreads();
        // issue into a buffer last consumed at iter c-1 (fenced by the
        // barrier above) -> single barrier per chunk.
        if (c < 2) {
            issueChunk(c + 2);
        } else if (FUSE && c == 2) {
            // W_out -> B buffer 1 (chunk 1's, dead; chunk 3 uses buffer 0)
            #pragma unroll
            for (int g = tid; g < 1024; g += 512) {
                int n = g >> 4, kk = (g & 15) * 8;
                int chunk = kk >> 6, lc = kk & 63;
                uint32_t doff = (uint32_t)(OFF_B + 16384 + chunk * 8192) +
                                SWZ((uint32_t)(n * 128 + lc * 2));
                cp16(sb + doff, WOh + n * 128 + kk);
            }
            CP_COMMIT;
        }
        const uint32_t ab = sb + (c % 3) * 16384;
        const uint32_t bb = sb + OFF_B + (c % 3) * 16384;
        #pragma unroll
        for (int ks = 0; ks < 4; ks++) {
            uint32_t ah[2][4], bh[4][2];
            const uint32_t ka = (a_base + ks * 32) ^ a_mask;
            #pragma unroll
            for (int mi = 0; mi < 2; mi++)
                ldsm4(ah[mi], ab + ka + mi * 2048);
            const uint32_t kb = (b_base + ks * 32) ^ b_mask;
            ldsm4(&bh[0][0], bb + kb);
            ldsm4(&bh[2][0], bb + kb + 2048);
            #pragma unroll
            for (int mi = 0; mi < 2; mi++)
                #pragma unroll
                for (int ni = 0; ni < 4; ni++)
                    mma16816(acc[mi][ni], ah[mi], bh[ni]);
        }
    }

    const int erow = wm + (lane >> 2);
    const int ecol = wn + (lane & 3) * 2;

    if (!FUSE) {
        // epilogue: bias (+relu) -> fp16 plane
        #pragma unroll
        for (int mi = 0; mi < 2; mi++) {
            #pragma unroll
            for (int h = 0; h < 2; h++) {
                const int gr = node0 + erow + mi * 16 + h * 8;
                if (gr >= N_NODES) continue;
                #pragma unroll
                for (int ni = 0; ni < 4; ni++) {
                    const int cc = ecol + ni * 8;
                    float ox = acc[mi][ni][2 * h] + sB[cc];
                    float oy = acc[mi][ni][2 * h + 1] + sB[cc + 1];
                    if (RELU) { ox = fmaxf(ox, 0.f); oy = fmaxf(oy, 0.f); }
                    *(uint32_t*)((char*)Y + ((size_t)gr * F + cc) * 2) =
                        pk_h(ox, oy);
                }
            }
        }
        return;
    }

    // ---- FUSE: pack h2 tile (bias, no relu) into smem fp16 ----------------
    // A buffers are all dead now: chunk c of h2 -> smc + c*16384 (A0,A1).
    __syncthreads();
    #pragma unroll
    for (int mi = 0; mi < 2; mi++) {
        #pragma unroll
        for (int h = 0; h < 2; h++) {
            const int r = erow + mi * 16 + h * 8;
            #pragma unroll
            for (int ni = 0; ni < 4; ni++) {
                const int cc = ecol + ni * 8;
                float ox = acc[mi][ni][2 * h] + sB[cc];
                float oy = acc[mi][ni][2 * h + 1] + sB[cc + 1];
                const int chunk = cc >> 6, lc = cc & 63;
                *(uint32_t*)(smc + chunk * 16384 +
                             SWZ((uint32_t)(r * 128 + lc * 2))) = pk_h(ox, oy);
            }
        }
    }
    __syncthreads();

    // ---- FUSE: h2 @ W_out + bout -> Yout (128 x 64, K=128) ----------------
    const int wn2 = (wid & 1) * 32;
    const int wm2 = (wid >> 1) * 16;
    const int ar2 = wm2 + (lane & 15);
    const uint32_t a_base2 = (uint32_t)(ar2 * 128 + (lane >> 4) * 16);
    const uint32_t a_mask2 = (uint32_t)((ar2 & 7) << 4);
    const int br2 = wn2 + (lane & 7) + ((lane >> 4) << 3);
    const uint32_t b_base2 = (uint32_t)(br2 * 128 + ((lane >> 3) & 1) * 16);
    const uint32_t b_mask2 = (uint32_t)((br2 & 7) << 4);

    float acc2[4][4];
    #pragma unroll
    for (int ni = 0; ni < 4; ni++)
        #pragma unroll
        for (int q = 0; q < 4; q++) acc2[ni][q] = 0.f;

    #pragma unroll
    for (int c = 0; c < 2; c++) {
        const uint32_t ab = sb + c * 16384;
        const uint32_t bb = sb + OFF_B + 16384 + c * 8192;  // WO in B buf 1
        #pragma unroll
        for (int ks = 0; ks < 4; ks++) {
            uint32_t ah[4], bh[4][2];
            ldsm4(ah, ab + ((a_base2 + ks * 32) ^ a_mask2));
            const uint32_t kb = (b_base2 + ks * 32) ^ b_mask2;
            ldsm4(&bh[0][0], bb + kb);
            ldsm4(&bh[2][0], bb + kb + 2048);
            #pragma unroll
            for (int ni = 0; ni < 4; ni++) mma16816(acc2[ni], ah, bh[ni]);
        }
    }

    const int erow2 = wm2 + (lane >> 2);
    const int ecol2 = wn2 + (lane & 3) * 2;
    #pragma unroll
    for (int h = 0; h < 2; h++) {
        const int gr = node0 + erow2 + h * 8;
        if (gr >= N_NODES) continue;
        float* yp = Yout + (size_t)gr * 64;
        #pragma unroll
        for (int ni = 0; ni < 4; ni++) {
            float2 o;
            o.x = acc2[ni][2 * h] + sBo[ecol2 + ni * 8];
            o.y = acc2[ni][2 * h + 1] + sBo[ecol2 + ni * 8 + 1];
            *(float2*)(yp + ecol2 + ni * 8) = o;
        }
    }
}

// ---------------------------------------------------------------------------
extern "C" void kernel_launch(void* const* d_in, const int* in_sizes, int n_in,
                              void* d_out, int out_size) {
    const float* feats = (const float*)d_in[0];
    const int* src = (const int*)d_in[1];
    const int* dst = (const int*)d_in[2];
    const float* Ws[3] = {(const float*)d_in[3], (const float*)d_in[7],
                          (const float*)d_in[11]};
    const float* bs[3] = {(const float*)d_in[4], (const float*)d_in[8],
                          (const float*)d_in[12]};
    const float* Wn[3] = {(const float*)d_in[5], (const float*)d_in[9],
                          (const float*)d_in[13]};
    const float* bn[3] = {(const float*)d_in[6], (const float*)d_in[10],
                          (const float*)d_in[14]};
    const float* Wout = (const float*)d_in[15];
    const float* bout = (const float*)d_in[16];

    __half *f, *h0, *h1, *a, *wh;
    cudaGetSymbolAddress((void**)&f, g_f);
    cudaGetSymbolAddress((void**)&h0, g_h0);
    cudaGetSymbolAddress((void**)&h1, g_h1);
    cudaGetSymbolAddress((void**)&a, g_a);
    cudaGetSymbolAddress((void**)&wh, g_wh);

    const int SMEM_GEMM = 98304 + 1024;  // 99,328 -> 2 CTAs/SM

    auto kRelu = sage_mma<true, false>;
    auto kFuse = sage_mma<false, true>;
    cudaFuncSetAttribute((const void*)kRelu,
                         cudaFuncAttributeMaxDynamicSharedMemorySize, SMEM_GEMM);
    cudaFuncSetAttribute((const void*)kFuse,
                         cudaFuncAttributeMaxDynamicSharedMemorySize, SMEM_GEMM);

    const int NPART = (N_NODES + 1023) / 1024;  // 98
    init_kernel<<<(N_NODES * 32 + 255) / 256, 256>>>(
        feats, Ws[0], Wn[0], Ws[1], Wn[1], Ws[2], Wn[2], Wout);
    count_kernel<<<(N_EDGES + 255) / 256, 256>>>(dst);
    scanall_kernel<<<NPART, 1024>>>();
    fill_kernel<<<(N_EDGES + 255) / 256, 256>>>(src, dst);

    const int AGG_BLOCKS = (N_NODES * 32 + 255) / 256;
    const int GB = (N_NODES + 127) / 128;  // 782

    agg_kernel<<<AGG_BLOCKS, 256>>>(f);
    kRelu<<<GB, 512, SMEM_GEMM>>>(f, a, wh, bs[0], bn[0], h0, nullptr, nullptr,
                                  nullptr);
    agg_kernel<<<AGG_BLOCKS, 256>>>(h0);
    kRelu<<<GB, 512, SMEM_GEMM>>>(h0, a, wh + 32768, bs[1], bn[1], h1, nullptr,
                                  nullptr, nullptr);
    agg_kernel<<<AGG_BLOCKS, 256>>>(h1);
    kFuse<<<GB, 512, SMEM_GEMM>>>(h1, a, wh + 65536, bs[2], bn[2], nullptr,
                                  wh + 98304, bout, (float*)d_out);
}